// round 12
// baseline (speedup 1.0000x reference)
#include <cuda_runtime.h>
#include <cuda_bf16.h>
#include <cstdint>

// Problem constants
#define BATCH 1024
#define NN    156
#define CIN   301
#define CH    128
#define EDGES 1564
#define ETOT  (EDGES + NN)      // 1720
#define MTOT  (BATCH * NN)      // 159744
#define BN_INV_SQRT 0.9999950000374997f

// W-chunk slots: L0 = 5 chunks (Kpad 320), L1 = 2, L2 = 2  -> 9 slots
#define NSLOT 9
#define CHUNK_ELEMS (128 * 64)   // bf16 per slot (per hi/lo)
#define AW 36                    // smem row stride in 32-bit words
#define AWB (AW * 4)             // 144 bytes

// ---------------- scratch (static device memory) ----------------------------
__device__ float g_T[(size_t)MTOT * CH];                // fp32 GEMM output
__device__ __nv_bfloat16 g_Hhi[(size_t)MTOT * CH];      // agg output, bf16 hi
__device__ __nv_bfloat16 g_Hlo[(size_t)MTOT * CH];      // agg output, bf16 lo
__device__ int   g_ptr[NN + 1];
__device__ int2  g_edge[ETOT];
__device__ __nv_bfloat16 g_WtHi[NSLOT * CHUNK_ELEMS];   // [slot][n][k] bf16
__device__ __nv_bfloat16 g_WtLo[NSLOT * CHUNK_ELEMS];

// ---------------- helpers ----------------------------------------------------
__device__ __forceinline__ uint32_t bf16x2_pack(float lo_elem, float hi_elem) {
    uint32_t r;
    asm("cvt.rn.bf16x2.f32 %0, %1, %2;" : "=r"(r) : "f"(hi_elem), "f"(lo_elem));
    return r;
}
__device__ __forceinline__ void mma16816(float* c, const uint32_t* a,
                                         uint32_t b0, uint32_t b1) {
    asm volatile(
        "mma.sync.aligned.m16n8k16.row.col.f32.bf16.bf16.f32 "
        "{%0,%1,%2,%3}, {%4,%5,%6,%7}, {%8,%9}, {%0,%1,%2,%3};"
        : "+f"(c[0]), "+f"(c[1]), "+f"(c[2]), "+f"(c[3])
        : "r"(a[0]), "r"(a[1]), "r"(a[2]), "r"(a[3]), "r"(b0), "r"(b1));
}
__device__ __forceinline__ void ldsm_x4(uint32_t* r, uint32_t addr) {
    asm volatile(
        "ldmatrix.sync.aligned.m8n8.x4.shared.b16 {%0,%1,%2,%3}, [%4];"
        : "=r"(r[0]), "=r"(r[1]), "=r"(r[2]), "=r"(r[3]) : "r"(addr));
}
__device__ __forceinline__ uint32_t smem_u32(const void* p) {
    uint32_t a;
    asm("{ .reg .u64 t; cvta.to.shared.u64 t, %1; cvt.u32.u64 %0, t; }"
        : "=r"(a) : "l"(p));
    return a;
}
__device__ __forceinline__ void cpa16(uint32_t d, const void* s) {
    asm volatile("cp.async.cg.shared.global [%0], [%1], 16;" :: "r"(d), "l"(s));
}
__device__ __forceinline__ void cpa4(uint32_t d, const void* s) {
    asm volatile("cp.async.ca.shared.global [%0], [%1], 4;" :: "r"(d), "l"(s));
}
#define CP_COMMIT asm volatile("cp.async.commit_group;" ::: "memory")
#define CP_WAIT0  asm volatile("cp.async.wait_group 0;" ::: "memory")

// shared ldmatrix/HMMA compute core: one 64-k chunk, 3 bf16 passes
__device__ __forceinline__ void compute_chunk(
    float acc[2][8][4],
    uint32_t aHi0, uint32_t aHi1, uint32_t aLo0, uint32_t aLo1,
    const uint32_t bHi[4], const uint32_t bLo[4])
{
#pragma unroll
    for (int ks = 0; ks < 4; ks++) {
        const uint32_t kb = (uint32_t)ks * 32;
        uint32_t ah[2][4], al[2][4];
        ldsm_x4(ah[0], aHi0 + kb);
        ldsm_x4(ah[1], aHi1 + kb);
        ldsm_x4(al[0], aLo0 + kb);
        ldsm_x4(al[1], aLo1 + kb);
#pragma unroll
        for (int nfp = 0; nfp < 4; nfp++) {
            uint32_t bh[4], bl[4];
            ldsm_x4(bh, bHi[nfp] + kb);
            ldsm_x4(bl, bLo[nfp] + kb);
#pragma unroll
            for (int h = 0; h < 2; h++) {
                int nf = nfp * 2 + h;
                uint32_t bh0 = bh[h * 2], bh1 = bh[h * 2 + 1];
                uint32_t bl0 = bl[h * 2], bl1 = bl[h * 2 + 1];
#pragma unroll
                for (int mf = 0; mf < 2; mf++) {
                    mma16816(acc[mf][nf], ah[mf], bh0, bh1);
                    mma16816(acc[mf][nf], ah[mf], bl0, bl1);
                    mma16816(acc[mf][nf], al[mf], bh0, bh1);
                }
            }
        }
    }
}

// ---------------- kernel 1: graph preprocessing -> packed CSC ---------------
__global__ void build_kernel(const void* __restrict__ eiv) {
    const int* e32 = (const int*)eiv;
    __shared__ int   is64;
    __shared__ float deg[NN];
    __shared__ float dinv[NN];
    __shared__ int   cnt[NN];
    __shared__ int   base[NN + 1];
    int tid = threadIdx.x;

    if (tid == 0) {
        int all_zero = 1;
        for (int i = 1; i < 129; i += 2)
            if (e32[i] != 0) { all_zero = 0; break; }
        is64 = all_zero;
    }
    if (tid < NN) { deg[tid] = 1.0f; cnt[tid] = 1; }
    __syncthreads();

    const int stride64 = is64;
    auto fetch = [&](int i) -> int {
        int v = e32[i << stride64];
        return min(max(v, 0), NN - 1);
    };

    for (int e = tid; e < EDGES; e += blockDim.x) {
        int cl = fetch(EDGES + e);
        atomicAdd(&deg[cl], 1.0f);
        atomicAdd(&cnt[cl], 1);
    }
    __syncthreads();
    if (tid < NN) dinv[tid] = rsqrtf(deg[tid]);
    if (tid == 0) {
        int run = 0;
        for (int n = 0; n < NN; n++) { base[n] = run; run += cnt[n]; }
        base[NN] = run;
    }
    __syncthreads();
    if (tid <= NN) g_ptr[tid] = base[tid];
    if (tid < NN) cnt[tid] = base[tid];
    __syncthreads();

    for (int e = tid; e < EDGES; e += blockDim.x) {
        int r  = fetch(e);
        int cl = fetch(EDGES + e);
        int pos = atomicAdd(&cnt[cl], 1);
        g_edge[pos] = make_int2(r, __float_as_int(dinv[r] * dinv[cl]));
    }
    __syncthreads();
    for (int n = tid; n < NN; n += blockDim.x) {
        int pos = atomicAdd(&cnt[n], 1);
        g_edge[pos] = make_int2(n, __float_as_int(dinv[n] * dinv[n]));
    }
}

// ---------------- kernel 2: W prep: split + transpose ------------------------
__global__ void wprep_kernel(const float* __restrict__ W0,
                             const float* __restrict__ W1,
                             const float* __restrict__ W2) {
    int gid = blockIdx.x * blockDim.x + threadIdx.x;
    if (gid >= NSLOT * CHUNK_ELEMS) return;
    int slot = gid >> 13;
    int rem  = gid & 8191;
    int n = rem >> 6;
    int k = rem & 63;
    const float* W; int K; int c0;
    if (slot < 5)      { W = W0; K = CIN; c0 = slot; }
    else if (slot < 7) { W = W1; K = CH;  c0 = slot - 5; }
    else               { W = W2; K = CH;  c0 = slot - 7; }
    int kg = c0 * 64 + k;
    float v = (kg < K) ? W[(size_t)kg * CH + n] : 0.0f;
    __nv_bfloat16 hi = __float2bfloat16(v);
    __nv_bfloat16 lo = __float2bfloat16(v - __bfloat162float(hi));
    g_WtHi[gid] = hi;
    g_WtLo[gid] = lo;
}

// ---------------- kernel 3a: L0 GEMM (fp32 A, cp.async + in-smem split) ------
// smem: A32 buf[2] [128][66]f (2x33792) | Ahi (18432) | Alo (18432)
//       | B buf[2] x (Bhi|Blo) (2x36864)  = 178176 B total.  1 CTA/SM.
#define L0_A32   0
#define L0_AHI   67584
#define L0_ALO   86016
#define L0_B     104448
#define GEMM_L0_SMEM 178176

__global__ void __launch_bounds__(256) gemm_l0(
    const float* __restrict__ A,
    const __nv_bfloat16* __restrict__ wtHi,
    const __nv_bfloat16* __restrict__ wtLo,
    float* __restrict__ out)
{
    extern __shared__ char smc[];
    const uint32_t s0 = smem_u32(smc);
    const int tid  = threadIdx.x;
    const int wid  = tid >> 5;
    const int lane = tid & 31;
    const int g    = lane >> 2;
    const int tig  = lane & 3;
    const int warpM = wid & 3;
    const int warpN = wid >> 2;
    const size_t m0 = (size_t)blockIdx.x * 128;
    const int nchunks = 5;

    float acc[2][8][4];
#pragma unroll
    for (int mf = 0; mf < 2; mf++)
#pragma unroll
        for (int nf = 0; nf < 8; nf++)
#pragma unroll
            for (int q = 0; q < 4; q++) acc[mf][nf][q] = 0.0f;

    // ldmatrix lane-relative offsets
    const int aRow = warpM * 32 + (lane & 7) + ((lane >> 3) & 1) * 8;
    const uint32_t aKoff = ((lane >> 4) & 1) * 16;
    const int bRow = warpN * 64 + (lane & 7) + ((lane >> 4) & 1) * 8;
    const uint32_t bKoff = ((lane >> 3) & 1) * 16;
    uint32_t aRel[2], bRel[4];
#pragma unroll
    for (int mf = 0; mf < 2; mf++)
        aRel[mf] = (uint32_t)(aRow + mf * 16) * AWB + aKoff;
#pragma unroll
    for (int nfp = 0; nfp < 4; nfp++)
        bRel[nfp] = (uint32_t)(bRow + nfp * 16) * AWB + bKoff;

    auto stage = [&](int t) {
        // A fp32 chunk -> A32[t&1], 4B granules (128 rows x 64 k = 8192 words)
        const uint32_t abase = s0 + L0_A32 + (uint32_t)(t & 1) * 33792;
#pragma unroll
        for (int p = 0; p < 32; p++) {
            int idx = tid + p * 256;
            int row = idx >> 6, kk = idx & 63;
            int kg = t * 64 + kk;
            uint32_t doff = (uint32_t)(row * 66 + kk) * 4;
            if (kg < CIN)
                cpa4(abase + doff, A + (m0 + row) * (size_t)CIN + kg);
            else
                *(float*)(smc + L0_A32 + (t & 1) * 33792 + doff) = 0.0f;
        }
        // B hi/lo -> B[t&1]: 2 arrays x 128 rows x 8 granules = 2048 items
        const uint32_t bbase = s0 + L0_B + (uint32_t)(t & 1) * 36864;
#pragma unroll
        for (int p = 0; p < 8; p++) {
            int idx = tid + p * 256;          // 0..2047
            int arr = idx >> 10;               // 0 hi, 1 lo
            int rem = idx & 1023;
            int row = rem >> 3, c = rem & 7;
            const __nv_bfloat16* ws = arr ? wtLo : wtHi;
            cpa16(bbase + (uint32_t)arr * 18432 + (uint32_t)row * AWB + c * 16,
                  (const char*)(ws + (size_t)t * CHUNK_ELEMS + row * 64) + c * 16);
        }
        CP_COMMIT;
    };
    auto split = [&](int t) {
        const float* a32 = (const float*)(smc + L0_A32 + (t & 1) * 33792);
        uint32_t* sAh = (uint32_t*)(smc + L0_AHI);
        uint32_t* sAl = (uint32_t*)(smc + L0_ALO);
#pragma unroll
        for (int p = 0; p < 16; p++) {
            int idx = tid + p * 256;
            int m = idx >> 5, kp = idx & 31;
            float2 v = *(const float2*)&a32[m * 66 + kp * 2];
            float h0 = __bfloat162float(__float2bfloat16(v.x));
            float h1 = __bfloat162float(__float2bfloat16(v.y));
            sAh[m * AW + kp] = bf16x2_pack(h0, h1);
            sAl[m * AW + kp] = bf16x2_pack(v.x - h0, v.y - h1);
        }
    };

    stage(0);
    for (int t = 0; t < nchunks; t++) {
        CP_WAIT0;
        __syncthreads();
        if (t + 1 < nchunks) stage(t + 1);
        split(t);
        __syncthreads();
        uint32_t bbase = s0 + L0_B + (uint32_t)(t & 1) * 36864;
        uint32_t bH[4], bL[4];
#pragma unroll
        for (int nfp = 0; nfp < 4; nfp++) {
            bH[nfp] = bbase + bRel[nfp];
            bL[nfp] = bbase + 18432 + bRel[nfp];
        }
        compute_chunk(acc,
                      s0 + L0_AHI + aRel[0], s0 + L0_AHI + aRel[1],
                      s0 + L0_ALO + aRel[0], s0 + L0_ALO + aRel[1],
                      bH, bL);
    }

    // epilogue
#pragma unroll
    for (int mf = 0; mf < 2; mf++) {
#pragma unroll
        for (int nf = 0; nf < 8; nf++) {
            int row = warpM * 32 + mf * 16 + g;
            int col = warpN * 64 + nf * 8 + tig * 2;
            float* o0 = out + (m0 + row) * CH + col;
            float* o1 = o0 + 8 * CH;
            *(float2*)o0 = make_float2(acc[mf][nf][0], acc[mf][nf][1]);
            *(float2*)o1 = make_float2(acc[mf][nf][2], acc[mf][nf][3]);
        }
    }
}

// ---------------- kernel 3b: pre-split GEMM (L1/L2, all-cp.async) ------------
// smem: buf[2] x { Ahi | Alo | Bhi | Blo } each [128][AW]w -> 2x73728.
#define PS_BUF 73728
#define GEMM_PS_SMEM (2 * PS_BUF)

__global__ void __launch_bounds__(256) gemm_ps(
    const __nv_bfloat16* __restrict__ aHi,
    const __nv_bfloat16* __restrict__ aLo,
    const __nv_bfloat16* __restrict__ wtHi,
    const __nv_bfloat16* __restrict__ wtLo,
    float* __restrict__ out)
{
    extern __shared__ char smc[];
    const uint32_t s0 = smem_u32(smc);
    const int tid  = threadIdx.x;
    const int wid  = tid >> 5;
    const int lane = tid & 31;
    const int g    = lane >> 2;
    const int tig  = lane & 3;
    const int warpM = wid & 3;
    const int warpN = wid >> 2;
    const size_t m0 = (size_t)blockIdx.x * 128;
    const int nchunks = 2;   // K = 128

    float acc[2][8][4];
#pragma unroll
    for (int mf = 0; mf < 2; mf++)
#pragma unroll
        for (int nf = 0; nf < 8; nf++)
#pragma unroll
            for (int q = 0; q < 4; q++) acc[mf][nf][q] = 0.0f;

    const int aRow = warpM * 32 + (lane & 7) + ((lane >> 3) & 1) * 8;
    const uint32_t aKoff = ((lane >> 4) & 1) * 16;
    const int bRow = warpN * 64 + (lane & 7) + ((lane >> 4) & 1) * 8;
    const uint32_t bKoff = ((lane >> 3) & 1) * 16;
    uint32_t aRel[2], bRel[4];
#pragma unroll
    for (int mf = 0; mf < 2; mf++)
        aRel[mf] = (uint32_t)(aRow + mf * 16) * AWB + aKoff;
#pragma unroll
    for (int nfp = 0; nfp < 4; nfp++)
        bRel[nfp] = (uint32_t)(bRow + nfp * 16) * AWB + bKoff;

    auto stage = [&](int t) {
        const uint32_t base = s0 + (uint32_t)(t & 1) * PS_BUF;
        // 4 arrays x 128 rows x 8 granules = 4096 items
#pragma unroll
        for (int p = 0; p < 16; p++) {
            int idx = tid + p * 256;          // 0..4095
            int arr = idx >> 10;               // 0 Ahi, 1 Alo, 2 Bhi, 3 Blo
            int rem = idx & 1023;
            int row = rem >> 3, c = rem & 7;
            uint32_t dst = base + (uint32_t)arr * 18432 +
                           (uint32_t)row * AWB + c * 16;
            const char* src;
            if (arr == 0)
                src = (const char*)(aHi + (m0 + row) * CH) + t * 128 + c * 16;
            else if (arr == 1)
                src = (const char*)(aLo + (m0 + row) * CH) + t * 128 + c * 16;
            else if (arr == 2)
                src = (const char*)(wtHi + (size_t)t * CHUNK_ELEMS + row * 64) + c * 16;
            else
                src = (const char*)(wtLo + (size_t)t * CHUNK_ELEMS + row * 64) + c * 16;
            cpa16(dst, src);
        }
        CP_COMMIT;
    };

    stage(0);
    for (int t = 0; t < nchunks; t++) {
        CP_WAIT0;
        __syncthreads();
        if (t + 1 < nchunks) stage(t + 1);
        const uint32_t base = s0 + (uint32_t)(t & 1) * PS_BUF;
        uint32_t bH[4], bL[4];
#pragma unroll
        for (int nfp = 0; nfp < 4; nfp++) {
            bH[nfp] = base + 36864 + bRel[nfp];
            bL[nfp] = base + 55296 + bRel[nfp];
        }
        compute_chunk(acc,
                      base + aRel[0], base + aRel[1],
                      base + 18432 + aRel[0], base + 18432 + aRel[1],
                      bH, bL);
    }

#pragma unroll
    for (int mf = 0; mf < 2; mf++) {
#pragma unroll
        for (int nf = 0; nf < 8; nf++) {
            int row = warpM * 32 + mf * 16 + g;
            int col = warpN * 64 + nf * 8 + tig * 2;
            float* o0 = out + (m0 + row) * CH + col;
            float* o1 = o0 + 8 * CH;
            *(float2*)o0 = make_float2(acc[mf][nf][0], acc[mf][nf][1]);
            *(float2*)o1 = make_float2(acc[mf][nf][2], acc[mf][nf][3]);
        }
    }
}

// ---------------- kernel 4: agg (smem staged, warp-per-row) ------------------
// mode 1: bias+BN+ReLU, emit bf16 hi/lo split (feeds gemm_ps).
// mode 0: bias only, emit fp32 (final output).
#define AGG_SMEM (NN * CH * 4 + ETOT * 8 + (NN + 1) * 4)

__global__ void __launch_bounds__(512, 2) agg_kernel(
    const float* __restrict__ T, float* __restrict__ outf,
    __nv_bfloat16* __restrict__ oh, __nv_bfloat16* __restrict__ ol,
    const float* __restrict__ bias,
    const float* __restrict__ bnw, const float* __restrict__ bnb,
    int mode)
{
    extern __shared__ float smf[];
    float4* Ts4   = (float4*)smf;                    // [NN*32]
    int2*   edg_s = (int2*)(smf + NN * CH);          // [ETOT]
    int*    ptr_s = (int*)(edg_s + ETOT);            // [NN+1]

    const int tid  = threadIdx.x;
    const int warp = tid >> 5;
    const int lane = tid & 31;
    const int b    = blockIdx.x;

    {
        const float4* Tb4 = (const float4*)(T + (size_t)b * NN * CH);
#pragma unroll
        for (int i = tid; i < NN * 32; i += 512) Ts4[i] = Tb4[i];
    }
    for (int i = tid; i < ETOT; i += 512) edg_s[i] = g_edge[i];
    if (tid <= NN) ptr_s[tid] = g_ptr[tid];
    __syncthreads();

    float4 bias4 = ((const float4*)bias)[lane];
    float4 bnw4 = make_float4(0, 0, 0, 0), bnb4 = make_float4(0, 0, 0, 0);
    if (mode) {
        bnw4 = ((const float4*)bnw)[lane];
        bnw4.x *= BN_INV_SQRT; bnw4.y *= BN_INV_SQRT;
        bnw4.z *= BN_INV_SQRT; bnw4.w *= BN_INV_SQRT;
        bnb4 = ((const float4*)bnb)[lane];
    }

    for (int n = warp; n < NN; n += 16) {
        int e = ptr_s[n];
        const int end = ptr_s[n + 1];
        float4 a0 = make_float4(0, 0, 0, 0);
        float4 a1 = make_float4(0, 0, 0, 0);
        for (; e + 1 < end; e += 2) {
            int2 e0 = edg_s[e], e1 = edg_s[e + 1];
            float4 t0 = Ts4[e0.x * 32 + lane];
            float4 t1 = Ts4[e1.x * 32 + lane];
            float m0 = __int_as_float(e0.y);
            float m1 = __int_as_float(e1.y);
            a0.x = fmaf(t0.x, m0, a0.x); a0.y = fmaf(t0.y, m0, a0.y);
            a0.z = fmaf(t0.z, m0, a0.z); a0.w = fmaf(t0.w, m0, a0.w);
            a1.x = fmaf(t1.x, m1, a1.x); a1.y = fmaf(t1.y, m1, a1.y);
            a1.z = fmaf(t1.z, m1, a1.z); a1.w = fmaf(t1.w, m1, a1.w);
        }
        if (e < end) {
            int2 e0 = edg_s[e];
            float4 t0 = Ts4[e0.x * 32 + lane];
            float m0 = __int_as_float(e0.y);
            a0.x = fmaf(t0.x, m0, a0.x); a0.y = fmaf(t0.y, m0, a0.y);
            a0.z = fmaf(t0.z, m0, a0.z); a0.w = fmaf(t0.w, m0, a0.w);
        }
        float4 v;
        v.x = a0.x + a1.x + bias4.x;
        v.y = a0.y + a1.y + bias4.y;
        v.z = a0.z + a1.z + bias4.z;
        v.w = a0.w + a1.w + bias4.w;
        const size_t ofs = (size_t)b * NN * CH + n * CH + lane * 4;
        if (mode) {
            v.x = fmaxf(fmaf(v.x, bnw4.x, bnb4.x), 0.0f);
            v.y = fmaxf(fmaf(v.y, bnw4.y, bnb4.y), 0.0f);
            v.z = fmaxf(fmaf(v.z, bnw4.z, bnb4.z), 0.0f);
            v.w = fmaxf(fmaf(v.w, bnw4.w, bnb4.w), 0.0f);
            __nv_bfloat16 hx = __float2bfloat16(v.x);
            __nv_bfloat16 hy = __float2bfloat16(v.y);
            __nv_bfloat16 hz = __float2bfloat16(v.z);
            __nv_bfloat16 hw = __float2bfloat16(v.w);
            float fx = __bfloat162float(hx), fy = __bfloat162float(hy);
            float fz = __bfloat162float(hz), fw = __bfloat162float(hw);
            uint2 hv, lv;
            hv.x = ((uint32_t)__bfloat16_as_ushort(hy) << 16) |
                   __bfloat16_as_ushort(hx);
            hv.y = ((uint32_t)__bfloat16_as_ushort(hw) << 16) |
                   __bfloat16_as_ushort(hz);
            lv.x = bf16x2_pack(v.x - fx, v.y - fy);
            lv.y = bf16x2_pack(v.z - fz, v.w - fw);
            *(uint2*)(oh + ofs) = hv;
            *(uint2*)(ol + ofs) = lv;
        } else {
            *(float4*)(outf + ofs) = v;
        }
    }
}

// ---------------- launch ----------------------------------------------------
extern "C" void kernel_launch(void* const* d_in, const int* in_sizes, int n_in,
                              void* d_out, int out_size)
{
    const float* x    = (const float*)d_in[0];
    const void*  ei   = d_in[1];
    const float* W0   = (const float*)d_in[2];
    const float* b0   = (const float*)d_in[3];
    const float* bnw0 = (const float*)d_in[4];
    const float* bnb0 = (const float*)d_in[5];
    const float* W1   = (const float*)d_in[6];
    const float* b1   = (const float*)d_in[7];
    const float* bnw1 = (const float*)d_in[8];
    const float* bnb1 = (const float*)d_in[9];
    const float* W2   = (const float*)d_in[10];
    const float* b2   = (const float*)d_in[11];
    float*       out  = (float*)d_out;

    float* t0;
    __nv_bfloat16 *hh, *hl, *wh, *wl;
    cudaGetSymbolAddress((void**)&t0, g_T);
    cudaGetSymbolAddress((void**)&hh, g_Hhi);
    cudaGetSymbolAddress((void**)&hl, g_Hlo);
    cudaGetSymbolAddress((void**)&wh, g_WtHi);
    cudaGetSymbolAddress((void**)&wl, g_WtLo);

    cudaFuncSetAttribute(gemm_l0,
                         cudaFuncAttributeMaxDynamicSharedMemorySize, GEMM_L0_SMEM);
    cudaFuncSetAttribute(gemm_ps,
                         cudaFuncAttributeMaxDynamicSharedMemorySize, GEMM_PS_SMEM);
    cudaFuncSetAttribute(agg_kernel,
                         cudaFuncAttributeMaxDynamicSharedMemorySize, AGG_SMEM);

    const int gridM = MTOT / 128;   // 1248

    // build duplicated (idempotent) so ncu's -s 5 -c 1 window captures gemm_ps.
    build_kernel<<<1, 256>>>(ei);                                     // 1
    build_kernel<<<1, 256>>>(ei);                                     // 2
    wprep_kernel<<<(NSLOT * CHUNK_ELEMS + 511) / 512, 512>>>(W0, W1, W2); // 3

    // layer 0
    gemm_l0<<<gridM, 256, GEMM_L0_SMEM>>>(x, wh, wl, t0);             // 4
    agg_kernel<<<BATCH, 512, AGG_SMEM>>>(t0, nullptr, hh, hl,
                                         b0, bnw0, bnb0, 1);          // 5
    // layer 1
    gemm_ps<<<gridM, 256, GEMM_PS_SMEM>>>(hh, hl,
        wh + 5 * CHUNK_ELEMS, wl + 5 * CHUNK_ELEMS, t0);              // 6 <- ncu
    agg_kernel<<<BATCH, 512, AGG_SMEM>>>(t0, nullptr, hh, hl,
                                         b1, bnw1, bnb1, 1);          // 7
    // layer 2
    gemm_ps<<<gridM, 256, GEMM_PS_SMEM>>>(hh, hl,
        wh + 7 * CHUNK_ELEMS, wl + 7 * CHUNK_ELEMS, t0);              // 8
    agg_kernel<<<BATCH, 512, AGG_SMEM>>>(t0, out, nullptr, nullptr,
                                         b2, nullptr, nullptr, 0);    // 9
}

// round 13
// speedup vs baseline: 1.0495x; 1.0495x over previous
#include <cuda_runtime.h>
#include <cuda_bf16.h>
#include <cstdint>

// Problem constants
#define BATCH 1024
#define NN    156
#define CIN   301
#define CH    128
#define EDGES 1564
#define ETOT  (EDGES + NN)      // 1720
#define MTOT  (BATCH * NN)      // 159744
#define BN_INV_SQRT 0.9999950000374997f

// W-chunk slots: L0 = 5 chunks (Kpad 320), L1 = 2, L2 = 2  -> 9 slots
#define NSLOT 9
#define CHUNK_ELEMS (128 * 64)   // bf16 per slot (per hi/lo)
#define AW 36                    // BK=64 row stride in 32-bit words
#define AWB (AW * 4)             // 144 bytes
#define AW2B 80                  // BK=32 row stride in bytes (20 words)

// ---------------- scratch (static device memory) ----------------------------
__device__ float g_T[(size_t)MTOT * CH];                // fp32 GEMM output
__device__ __nv_bfloat16 g_Hhi[(size_t)MTOT * CH];      // agg output, bf16 hi
__device__ __nv_bfloat16 g_Hlo[(size_t)MTOT * CH];      // agg output, bf16 lo
__device__ int   g_ptr[NN + 1];
__device__ int2  g_edge[ETOT];
__device__ __nv_bfloat16 g_WtHi[NSLOT * CHUNK_ELEMS];   // [slot][n][k] bf16
__device__ __nv_bfloat16 g_WtLo[NSLOT * CHUNK_ELEMS];

// ---------------- helpers ----------------------------------------------------
__device__ __forceinline__ uint32_t bf16x2_pack(float lo_elem, float hi_elem) {
    uint32_t r;
    asm("cvt.rn.bf16x2.f32 %0, %1, %2;" : "=r"(r) : "f"(hi_elem), "f"(lo_elem));
    return r;
}
__device__ __forceinline__ void mma16816(float* c, const uint32_t* a,
                                         uint32_t b0, uint32_t b1) {
    asm volatile(
        "mma.sync.aligned.m16n8k16.row.col.f32.bf16.bf16.f32 "
        "{%0,%1,%2,%3}, {%4,%5,%6,%7}, {%8,%9}, {%0,%1,%2,%3};"
        : "+f"(c[0]), "+f"(c[1]), "+f"(c[2]), "+f"(c[3])
        : "r"(a[0]), "r"(a[1]), "r"(a[2]), "r"(a[3]), "r"(b0), "r"(b1));
}
__device__ __forceinline__ void ldsm_x4(uint32_t* r, uint32_t addr) {
    asm volatile(
        "ldmatrix.sync.aligned.m8n8.x4.shared.b16 {%0,%1,%2,%3}, [%4];"
        : "=r"(r[0]), "=r"(r[1]), "=r"(r[2]), "=r"(r[3]) : "r"(addr));
}
__device__ __forceinline__ uint32_t smem_u32(const void* p) {
    uint32_t a;
    asm("{ .reg .u64 t; cvta.to.shared.u64 t, %1; cvt.u32.u64 %0, t; }"
        : "=r"(a) : "l"(p));
    return a;
}
__device__ __forceinline__ void cpa16(uint32_t d, const void* s) {
    asm volatile("cp.async.cg.shared.global [%0], [%1], 16;" :: "r"(d), "l"(s));
}
#define CP_COMMIT asm volatile("cp.async.commit_group;" ::: "memory")
#define CP_WAIT0  asm volatile("cp.async.wait_group 0;" ::: "memory")
#define CP_WAIT1  asm volatile("cp.async.wait_group 1;" ::: "memory")

// ---------------- kernel 1: graph preprocessing -> packed CSC ---------------
__global__ void build_kernel(const void* __restrict__ eiv) {
    const int* e32 = (const int*)eiv;
    __shared__ int   is64;
    __shared__ float deg[NN];
    __shared__ float dinv[NN];
    __shared__ int   cnt[NN];
    __shared__ int   base[NN + 1];
    int tid = threadIdx.x;

    if (tid == 0) {
        int all_zero = 1;
        for (int i = 1; i < 129; i += 2)
            if (e32[i] != 0) { all_zero = 0; break; }
        is64 = all_zero;
    }
    if (tid < NN) { deg[tid] = 1.0f; cnt[tid] = 1; }
    __syncthreads();

    const int stride64 = is64;
    auto fetch = [&](int i) -> int {
        int v = e32[i << stride64];
        return min(max(v, 0), NN - 1);
    };

    for (int e = tid; e < EDGES; e += blockDim.x) {
        int cl = fetch(EDGES + e);
        atomicAdd(&deg[cl], 1.0f);
        atomicAdd(&cnt[cl], 1);
    }
    __syncthreads();
    if (tid < NN) dinv[tid] = rsqrtf(deg[tid]);
    if (tid == 0) {
        int run = 0;
        for (int n = 0; n < NN; n++) { base[n] = run; run += cnt[n]; }
        base[NN] = run;
    }
    __syncthreads();
    if (tid <= NN) g_ptr[tid] = base[tid];
    if (tid < NN) cnt[tid] = base[tid];
    __syncthreads();

    for (int e = tid; e < EDGES; e += blockDim.x) {
        int r  = fetch(e);
        int cl = fetch(EDGES + e);
        int pos = atomicAdd(&cnt[cl], 1);
        g_edge[pos] = make_int2(r, __float_as_int(dinv[r] * dinv[cl]));
    }
    __syncthreads();
    for (int n = tid; n < NN; n += blockDim.x) {
        int pos = atomicAdd(&cnt[n], 1);
        g_edge[pos] = make_int2(n, __float_as_int(dinv[n] * dinv[n]));
    }
}

// ---------------- kernel 2: W prep: split + transpose ------------------------
__global__ void wprep_kernel(const float* __restrict__ W0,
                             const float* __restrict__ W1,
                             const float* __restrict__ W2) {
    int gid = blockIdx.x * blockDim.x + threadIdx.x;
    if (gid >= NSLOT * CHUNK_ELEMS) return;
    int slot = gid >> 13;
    int rem  = gid & 8191;
    int n = rem >> 6;
    int k = rem & 63;
    const float* W; int K; int c0;
    if (slot < 5)      { W = W0; K = CIN; c0 = slot; }
    else if (slot < 7) { W = W1; K = CH;  c0 = slot - 5; }
    else               { W = W2; K = CH;  c0 = slot - 7; }
    int kg = c0 * 64 + k;
    float v = (kg < K) ? W[(size_t)kg * CH + n] : 0.0f;
    __nv_bfloat16 hi = __float2bfloat16(v);
    __nv_bfloat16 lo = __float2bfloat16(v - __bfloat162float(hi));
    g_WtHi[gid] = hi;
    g_WtLo[gid] = lo;
}

// ---------------- kernel 3a: L0 GEMM (R10-proven, 2 CTA/SM) ------------------
// out[M,128] = A[M,K] @ W[K,128] fp32, 3x bf16 mma.sync passes.
// smem: Ahi | Alo | Bhi | Blo, each [128][AW] u32 words -> 73728 B.
#define GEMM_L0_SMEM (4 * 128 * AW * 4)

__global__ void __launch_bounds__(256, 2) gemm_l0(
    const float* __restrict__ A, int K, int nchunks,
    const __nv_bfloat16* __restrict__ wtHi,
    const __nv_bfloat16* __restrict__ wtLo,
    float* __restrict__ out)
{
    extern __shared__ uint32_t sml0[];
    uint32_t* sAh = sml0;
    uint32_t* sAl = sml0 + 128 * AW;
    uint32_t* sBh = sml0 + 2 * 128 * AW;
    uint32_t* sBl = sml0 + 3 * 128 * AW;

    const int tid  = threadIdx.x;
    const int wid  = tid >> 5;
    const int lane = tid & 31;
    const int g    = lane >> 2;
    const int tig  = lane & 3;
    const int warpM = wid & 3;
    const int warpN = wid >> 2;
    const size_t m0 = (size_t)blockIdx.x * 128;

    float acc[2][8][4];
#pragma unroll
    for (int mf = 0; mf < 2; mf++)
#pragma unroll
        for (int nf = 0; nf < 8; nf++)
#pragma unroll
            for (int q = 0; q < 4; q++) acc[mf][nf][q] = 0.0f;

    const uint32_t* gh32 = (const uint32_t*)wtHi;
    const uint32_t* gl32 = (const uint32_t*)wtLo;

    const int aRow = warpM * 32 + (lane & 7) + ((lane >> 3) & 1) * 8;
    const uint32_t aKoff = ((lane >> 4) & 1) * 16;
    const int bRow = warpN * 64 + (lane & 7) + ((lane >> 4) & 1) * 8;
    const uint32_t bKoff = ((lane >> 3) & 1) * 16;

    const uint32_t sAh_u = smem_u32(sAh), sAl_u = smem_u32(sAl);
    const uint32_t sBh_u = smem_u32(sBh), sBl_u = smem_u32(sBl);
    uint32_t aHiB[2], aLoB[2], bHiB[4], bLoB[4];
#pragma unroll
    for (int mf = 0; mf < 2; mf++) {
        uint32_t off = (uint32_t)(aRow + mf * 16) * AWB + aKoff;
        aHiB[mf] = sAh_u + off;
        aLoB[mf] = sAl_u + off;
    }
#pragma unroll
    for (int nfp = 0; nfp < 4; nfp++) {
        uint32_t off = (uint32_t)(bRow + nfp * 16) * AWB + bKoff;
        bHiB[nfp] = sBh_u + off;
        bLoB[nfp] = sBl_u + off;
    }

    for (int t = 0; t < nchunks; t++) {
        if (t) __syncthreads();

        // stage A (split fp32 -> bf16 hi/lo)
#pragma unroll
        for (int p = 0; p < 16; p++) {
            int idx = tid + p * 256;
            int m = idx >> 5, kp = idx & 31;
            int kg = t * 64 + kp * 2;
            const float* ap = A + (m0 + m) * (size_t)K + kg;
            float v0 = (kg < K)     ? ap[0] : 0.0f;
            float v1 = (kg + 1 < K) ? ap[1] : 0.0f;
            float h0f = __bfloat162float(__float2bfloat16(v0));
            float h1f = __bfloat162float(__float2bfloat16(v1));
            sAh[m * AW + kp] = bf16x2_pack(h0f, h1f);
            sAl[m * AW + kp] = bf16x2_pack(v0 - h0f, v1 - h1f);
        }
        // stage B
        const uint32_t* gh = gh32 + t * 4096;
        const uint32_t* gl = gl32 + t * 4096;
#pragma unroll
        for (int p = 0; p < 16; p++) {
            int idx = tid + p * 256;
            int n = idx >> 5, w = idx & 31;
            sBh[n * AW + w] = gh[n * 32 + w];
            sBl[n * AW + w] = gl[n * 32 + w];
        }
        __syncthreads();

        // compute: 4 k16 steps
#pragma unroll
        for (int ks = 0; ks < 4; ks++) {
            const uint32_t kb = (uint32_t)ks * 32;
            uint32_t ah[2][4], al[2][4];
            ldsm_x4(ah[0], aHiB[0] + kb);
            ldsm_x4(ah[1], aHiB[1] + kb);
            ldsm_x4(al[0], aLoB[0] + kb);
            ldsm_x4(al[1], aLoB[1] + kb);
#pragma unroll
            for (int nfp = 0; nfp < 4; nfp++) {
                uint32_t bh[4], bl[4];
                ldsm_x4(bh, bHiB[nfp] + kb);
                ldsm_x4(bl, bLoB[nfp] + kb);
#pragma unroll
                for (int h = 0; h < 2; h++) {
                    int nf = nfp * 2 + h;
                    uint32_t bh0 = bh[h * 2], bh1 = bh[h * 2 + 1];
                    uint32_t bl0 = bl[h * 2], bl1 = bl[h * 2 + 1];
#pragma unroll
                    for (int mf = 0; mf < 2; mf++) {
                        mma16816(acc[mf][nf], ah[mf], bh0, bh1);
                        mma16816(acc[mf][nf], ah[mf], bl0, bl1);
                        mma16816(acc[mf][nf], al[mf], bh0, bh1);
                    }
                }
            }
        }
    }

#pragma unroll
    for (int mf = 0; mf < 2; mf++) {
#pragma unroll
        for (int nf = 0; nf < 8; nf++) {
            int row = warpM * 32 + mf * 16 + g;
            int col = warpN * 64 + nf * 8 + tig * 2;
            float* o0 = out + (m0 + row) * CH + col;
            float* o1 = o0 + 8 * CH;
            *(float2*)o0 = make_float2(acc[mf][nf][0], acc[mf][nf][1]);
            *(float2*)o1 = make_float2(acc[mf][nf][2], acc[mf][nf][3]);
        }
    }
}

// ---------------- kernel 3b: pre-split GEMM, BK=32 double-buffered -----------
// smem: buf[2] x { Ahi | Alo | Bhi | Blo } each [128][20 words] -> 2x40960 B.
// 80KB/CTA -> 2 CTA/SM AND intra-CTA cp.async pipelining.
#define PS2_ARR 10240
#define PS2_BUF (4 * PS2_ARR)
#define GEMM_PS_SMEM (2 * PS2_BUF)

__global__ void __launch_bounds__(256, 2) gemm_ps(
    const __nv_bfloat16* __restrict__ aHi,
    const __nv_bfloat16* __restrict__ aLo,
    const __nv_bfloat16* __restrict__ wtHi,
    const __nv_bfloat16* __restrict__ wtLo,
    float* __restrict__ out)
{
    extern __shared__ char smps[];
    const uint32_t s0 = smem_u32(smps);
    const int tid  = threadIdx.x;
    const int wid  = tid >> 5;
    const int lane = tid & 31;
    const int g    = lane >> 2;
    const int tig  = lane & 3;
    const int warpM = wid & 3;
    const int warpN = wid >> 2;
    const size_t m0 = (size_t)blockIdx.x * 128;
    const int nchunks = 4;   // K=128, BK=32

    float acc[2][8][4];
#pragma unroll
    for (int mf = 0; mf < 2; mf++)
#pragma unroll
        for (int nf = 0; nf < 8; nf++)
#pragma unroll
            for (int q = 0; q < 4; q++) acc[mf][nf][q] = 0.0f;

    const int aRow = warpM * 32 + (lane & 7) + ((lane >> 3) & 1) * 8;
    const uint32_t aKoff = ((lane >> 4) & 1) * 16;
    const int bRow = warpN * 64 + (lane & 7) + ((lane >> 4) & 1) * 8;
    const uint32_t bKoff = ((lane >> 3) & 1) * 16;
    uint32_t aRel[2], bRel[4];
#pragma unroll
    for (int mf = 0; mf < 2; mf++)
        aRel[mf] = (uint32_t)(aRow + mf * 16) * AW2B + aKoff;
#pragma unroll
    for (int nfp = 0; nfp < 4; nfp++)
        bRel[nfp] = (uint32_t)(bRow + nfp * 16) * AW2B + bKoff;

    auto stage = [&](int t) {
        const uint32_t base = s0 + (uint32_t)(t & 1) * PS2_BUF;
        // 4 arrays x 128 rows x 4 granules(16B) = 2048 items
#pragma unroll
        for (int p = 0; p < 8; p++) {
            int idx = tid + p * 256;          // 0..2047
            int arr = idx >> 9;
            int rem = idx & 511;
            int row = rem >> 2, gg = rem & 3;
            uint32_t dst = base + (uint32_t)arr * PS2_ARR +
                           (uint32_t)row * AW2B + gg * 16;
            const char* src;
            if (arr == 0)
                src = (const char*)(aHi + (m0 + row) * CH) + t * 64 + gg * 16;
            else if (arr == 1)
                src = (const char*)(aLo + (m0 + row) * CH) + t * 64 + gg * 16;
            else if (arr == 2)
                src = (const char*)(wtHi + (size_t)(t >> 1) * CHUNK_ELEMS +
                                    row * 64 + (t & 1) * 32) + gg * 16;
            else
                src = (const char*)(wtLo + (size_t)(t >> 1) * CHUNK_ELEMS +
                                    row * 64 + (t & 1) * 32) + gg * 16;
            cpa16(dst, src);
        }
        CP_COMMIT;
    };

    stage(0);
    for (int t = 0; t < nchunks; t++) {
        if (t + 1 < nchunks) { stage(t + 1); CP_WAIT1; }
        else                 { CP_WAIT0; }
        __syncthreads();

        const uint32_t base = s0 + (uint32_t)(t & 1) * PS2_BUF;
#pragma unroll
        for (int ks = 0; ks < 2; ks++) {
            const uint32_t kb = (uint32_t)ks * 32;
            uint32_t ah[2][4], al[2][4];
            ldsm_x4(ah[0], base + aRel[0] + kb);
            ldsm_x4(ah[1], base + aRel[1] + kb);
            ldsm_x4(al[0], base + PS2_ARR + aRel[0] + kb);
            ldsm_x4(al[1], base + PS2_ARR + aRel[1] + kb);
#pragma unroll
            for (int nfp = 0; nfp < 4; nfp++) {
                uint32_t bh[4], bl[4];
                ldsm_x4(bh, base + 2 * PS2_ARR + bRel[nfp] + kb);
                ldsm_x4(bl, base + 3 * PS2_ARR + bRel[nfp] + kb);
#pragma unroll
                for (int h = 0; h < 2; h++) {
                    int nf = nfp * 2 + h;
                    uint32_t bh0 = bh[h * 2], bh1 = bh[h * 2 + 1];
                    uint32_t bl0 = bl[h * 2], bl1 = bl[h * 2 + 1];
#pragma unroll
                    for (int mf = 0; mf < 2; mf++) {
                        mma16816(acc[mf][nf], ah[mf], bh0, bh1);
                        mma16816(acc[mf][nf], ah[mf], bl0, bl1);
                        mma16816(acc[mf][nf], al[mf], bh0, bh1);
                    }
                }
            }
        }
        __syncthreads();   // all reads of buf t done before stage(t+2) next iter
    }

#pragma unroll
    for (int mf = 0; mf < 2; mf++) {
#pragma unroll
        for (int nf = 0; nf < 8; nf++) {
            int row = warpM * 32 + mf * 16 + g;
            int col = warpN * 64 + nf * 8 + tig * 2;
            float* o0 = out + (m0 + row) * CH + col;
            float* o1 = o0 + 8 * CH;
            *(float2*)o0 = make_float2(acc[mf][nf][0], acc[mf][nf][1]);
            *(float2*)o1 = make_float2(acc[mf][nf][2], acc[mf][nf][3]);
        }
    }
}

// ---------------- kernel 4: agg, channel-split (grid BATCH x 2) --------------
// Each CTA handles 64 channels of one batch; smem 54KB -> 4 CTA/SM.
#define AGG_SMEM (NN * 64 * 4 + ETOT * 8 + (NN + 1) * 4)

__global__ void __launch_bounds__(256) agg_kernel(
    const float* __restrict__ T, float* __restrict__ outf,
    __nv_bfloat16* __restrict__ oh, __nv_bfloat16* __restrict__ ol,
    const float* __restrict__ bias,
    const float* __restrict__ bnw, const float* __restrict__ bnb,
    int mode)
{
    extern __shared__ float smf[];
    float* Ts    = smf;                              // [NN*64]
    int2*  edg_s = (int2*)(smf + NN * 64);           // [ETOT]
    int*   ptr_s = (int*)(edg_s + ETOT);             // [NN+1]

    const int tid  = threadIdx.x;
    const int warp = tid >> 5;
    const int lane = tid & 31;
    const int b    = blockIdx.x;
    const int half = blockIdx.y;

    // stage half-channel tile (float4, coalesced in 256B runs)
    {
        const float4* Tb4 = (const float4*)(T + (size_t)b * NN * CH);
        float4* Ts4 = (float4*)Ts;
#pragma unroll
        for (int i = tid; i < NN * 16; i += 256) {
            int r = i >> 4, c = i & 15;
            Ts4[i] = Tb4[r * 32 + half * 16 + c];
        }
    }
    for (int i = tid; i < ETOT; i += 256) edg_s[i] = g_edge[i];
    if (tid <= NN) ptr_s[tid] = g_ptr[tid];
    __syncthreads();

    const int cbase = half * 64 + lane * 2;
    float2 bias2 = *(const float2*)&bias[cbase];
    float2 bnw2 = make_float2(0, 0), bnb2 = make_float2(0, 0);
    if (mode) {
        bnw2 = *(const float2*)&bnw[cbase];
        bnw2.x *= BN_INV_SQRT; bnw2.y *= BN_INV_SQRT;
        bnb2 = *(const float2*)&bnb[cbase];
    }

    const float2* Ts2 = (const float2*)Ts;   // row pitch 32 float2
    for (int n = warp; n < NN; n += 8) {
        int e = ptr_s[n];
        const int end = ptr_s[n + 1];
        float2 a0 = make_float2(0, 0);
        float2 a1 = make_float2(0, 0);
        for (; e + 1 < end; e += 2) {
            int2 e0 = edg_s[e], e1 = edg_s[e + 1];
            float2 t0 = Ts2[e0.x * 32 + lane];
            float2 t1 = Ts2[e1.x * 32 + lane];
            float m0 = __int_as_float(e0.y);
            float m1 = __int_as_float(e1.y);
            a0.x = fmaf(t0.x, m0, a0.x); a0.y = fmaf(t0.y, m0, a0.y);
            a1.x = fmaf(t1.x, m1, a1.x); a1.y = fmaf(t1.y, m1, a1.y);
        }
        if (e < end) {
            int2 e0 = edg_s[e];
            float2 t0 = Ts2[e0.x * 32 + lane];
            float m0 = __int_as_float(e0.y);
            a0.x = fmaf(t0.x, m0, a0.x); a0.y = fmaf(t0.y, m0, a0.y);
        }
        float2 v;
        v.x = a0.x + a1.x + bias2.x;
        v.y = a0.y + a1.y + bias2.y;
        const size_t ofs = (size_t)b * NN * CH + n * CH + cbase;
        if (mode) {
            v.x = fmaxf(fmaf(v.x, bnw2.x, bnb2.x), 0.0f);
            v.y = fmaxf(fmaf(v.y, bnw2.y, bnb2.y), 0.0f);
            __nv_bfloat16 hx = __float2bfloat16(v.x);
            __nv_bfloat16 hy = __float2bfloat16(v.y);
            float fx = __bfloat162float(hx), fy = __bfloat162float(hy);
            uint32_t hv = ((uint32_t)__bfloat16_as_ushort(hy) << 16) |
                          __bfloat16_as_ushort(hx);
            uint32_t lv = bf16x2_pack(v.x - fx, v.y - fy);
            *(uint32_t*)(oh + ofs) = hv;
            *(uint32_t*)(ol + ofs) = lv;
        } else {
            *(float2*)(outf + ofs) = v;
        }
    }
}

// ---------------- launch ----------------------------------------------------
extern "C" void kernel_launch(void* const* d_in, const int* in_sizes, int n_in,
                              void* d_out, int out_size)
{
    const float* x    = (const float*)d_in[0];
    const void*  ei   = d_in[1];
    const float* W0   = (const float*)d_in[2];
    const float* b0   = (const float*)d_in[3];
    const float* bnw0 = (const float*)d_in[4];
    const float* bnb0 = (const float*)d_in[5];
    const float* W1   = (const float*)d_in[6];
    const float* b1   = (const float*)d_in[7];
    const float* bnw1 = (const float*)d_in[8];
    const float* bnb1 = (const float*)d_in[9];
    const float* W2   = (const float*)d_in[10];
    const float* b2   = (const float*)d_in[11];
    float*       out  = (float*)d_out;

    float* t0;
    __nv_bfloat16 *hh, *hl, *wh, *wl;
    cudaGetSymbolAddress((void**)&t0, g_T);
    cudaGetSymbolAddress((void**)&hh, g_Hhi);
    cudaGetSymbolAddress((void**)&hl, g_Hlo);
    cudaGetSymbolAddress((void**)&wh, g_WtHi);
    cudaGetSymbolAddress((void**)&wl, g_WtLo);

    cudaFuncSetAttribute(gemm_l0,
                         cudaFuncAttributeMaxDynamicSharedMemorySize, GEMM_L0_SMEM);
    cudaFuncSetAttribute(gemm_ps,
                         cudaFuncAttributeMaxDynamicSharedMemorySize, GEMM_PS_SMEM);
    cudaFuncSetAttribute(agg_kernel,
                         cudaFuncAttributeMaxDynamicSharedMemorySize, AGG_SMEM);

    const int gridM = MTOT / 128;   // 1248
    dim3 agrid(BATCH, 2);

    // build x2 (idempotent) so ncu -s 5 -c 1 captures gemm_ps (launch #6).
    build_kernel<<<1, 256>>>(ei);                                     // 1
    build_kernel<<<1, 256>>>(ei);                                     // 2
    wprep_kernel<<<(NSLOT * CHUNK_ELEMS + 511) / 512, 512>>>(W0, W1, W2); // 3

    // layer 0
    gemm_l0<<<gridM, 256, GEMM_L0_SMEM>>>(x, CIN, 5, wh, wl, t0);     // 4
    agg_kernel<<<agrid, 256, AGG_SMEM>>>(t0, nullptr, hh, hl,
                                         b0, bnw0, bnb0, 1);          // 5
    // layer 1
    gemm_ps<<<gridM, 256, GEMM_PS_SMEM>>>(hh, hl,
        wh + 5 * CHUNK_ELEMS, wl + 5 * CHUNK_ELEMS, t0);              // 6 <- ncu
    agg_kernel<<<agrid, 256, AGG_SMEM>>>(t0, nullptr, hh, hl,
                                         b1, bnw1, bnb1, 1);          // 7
    // layer 2
    gemm_ps<<<gridM, 256, GEMM_PS_SMEM>>>(hh, hl,
        wh + 7 * CHUNK_ELEMS, wl + 7 * CHUNK_ELEMS, t0);              // 8
    agg_kernel<<<agrid, 256, AGG_SMEM>>>(t0, out, nullptr, nullptr,
                                         b2, nullptr, nullptr, 0);    // 9
}

// round 16
// speedup vs baseline: 1.2148x; 1.1576x over previous
#include <cuda_runtime.h>
#include <cuda_bf16.h>
#include <cstdint>

// Problem constants
#define BATCH 1024
#define NN    156
#define MT    160               // padded M tile
#define CIN   301
#define CH    128
#define EDGES 1564
#define ETOT  (EDGES + NN)      // 1720
#define MTOT  (BATCH * NN)
#define BN_INV_SQRT 0.9999950000374997f

#define NSLOT 9
#define CHUNK_ELEMS (128 * 64)   // bf16 per slot (per hi/lo)
#define AW 36                    // smem row stride, 32-bit words (BK=64)
#define AWB 144                  // bytes

// smem layout (bytes)
#define OFF_AH 0                 // 160*144 = 23040
#define OFF_AL 23040
#define OFF_BH 46080             // 128*144 = 18432
#define OFF_BL 64512
#define OFF_T  0                 // fp32 [156][132] = 82368 (overlays A/B)
#define OFF_EDG 82944            // int2[1720] = 13760
#define OFF_PTR 96704            // int[157]
#define SMEM_FUSED 97344

// ---------------- scratch (static device memory) ----------------------------
__device__ __nv_bfloat16 g_Hhi[(size_t)MTOT * CH];
__device__ __nv_bfloat16 g_Hlo[(size_t)MTOT * CH];
__device__ int   g_ptr[NN + 1];
__device__ int2  g_edge[ETOT];
__device__ __nv_bfloat16 g_WtHi[NSLOT * CHUNK_ELEMS];   // [slot][n][k]
__device__ __nv_bfloat16 g_WtLo[NSLOT * CHUNK_ELEMS];

// ---------------- helpers ----------------------------------------------------
__device__ __forceinline__ uint32_t bf16x2_pack(float lo_elem, float hi_elem) {
    uint32_t r;
    asm("cvt.rn.bf16x2.f32 %0, %1, %2;" : "=r"(r) : "f"(hi_elem), "f"(lo_elem));
    return r;
}
__device__ __forceinline__ void mma16816(float* c, const uint32_t* a,
                                         uint32_t b0, uint32_t b1) {
    asm volatile(
        "mma.sync.aligned.m16n8k16.row.col.f32.bf16.bf16.f32 "
        "{%0,%1,%2,%3}, {%4,%5,%6,%7}, {%8,%9}, {%0,%1,%2,%3};"
        : "+f"(c[0]), "+f"(c[1]), "+f"(c[2]), "+f"(c[3])
        : "r"(a[0]), "r"(a[1]), "r"(a[2]), "r"(a[3]), "r"(b0), "r"(b1));
}
__device__ __forceinline__ void ldsm_x4(uint32_t* r, uint32_t addr) {
    asm volatile(
        "ldmatrix.sync.aligned.m8n8.x4.shared.b16 {%0,%1,%2,%3}, [%4];"
        : "=r"(r[0]), "=r"(r[1]), "=r"(r[2]), "=r"(r[3]) : "r"(addr));
}
__device__ __forceinline__ uint32_t smem_u32(const void* p) {
    uint32_t a;
    asm("{ .reg .u64 t; cvta.to.shared.u64 t, %1; cvt.u32.u64 %0, t; }"
        : "=r"(a) : "l"(p));
    return a;
}

// ---------------- kernel 1: graph preprocessing -> packed CSC ---------------
__global__ void build_kernel(const void* __restrict__ eiv) {
    const int* e32 = (const int*)eiv;
    __shared__ int   is64;
    __shared__ float deg[NN];
    __shared__ float dinv[NN];
    __shared__ int   cnt[NN];
    __shared__ int   base[NN + 1];
    int tid = threadIdx.x;

    if (tid == 0) {
        int all_zero = 1;
        for (int i = 1; i < 129; i += 2)
            if (e32[i] != 0) { all_zero = 0; break; }
        is64 = all_zero;
    }
    if (tid < NN) { deg[tid] = 1.0f; cnt[tid] = 1; }
    __syncthreads();

    const int stride64 = is64;
    auto fetch = [&](int i) -> int {
        int v = e32[i << stride64];
        return min(max(v, 0), NN - 1);
    };

    for (int e = tid; e < EDGES; e += blockDim.x) {
        int cl = fetch(EDGES + e);
        atomicAdd(&deg[cl], 1.0f);
        atomicAdd(&cnt[cl], 1);
    }
    __syncthreads();
    if (tid < NN) dinv[tid] = rsqrtf(deg[tid]);
    if (tid == 0) {
        int run = 0;
        for (int n = 0; n < NN; n++) { base[n] = run; run += cnt[n]; }
        base[NN] = run;
    }
    __syncthreads();
    if (tid <= NN) g_ptr[tid] = base[tid];
    if (tid < NN) cnt[tid] = base[tid];
    __syncthreads();

    for (int e = tid; e < EDGES; e += blockDim.x) {
        int r  = fetch(e);
        int cl = fetch(EDGES + e);
        int pos = atomicAdd(&cnt[cl], 1);
        g_edge[pos] = make_int2(r, __float_as_int(dinv[r] * dinv[cl]));
    }
    __syncthreads();
    for (int n = tid; n < NN; n += blockDim.x) {
        int pos = atomicAdd(&cnt[n], 1);
        g_edge[pos] = make_int2(n, __float_as_int(dinv[n] * dinv[n]));
    }
}

// ---------------- kernel 2: W prep: split + transpose ------------------------
__global__ void wprep_kernel(const float* __restrict__ W0,
                             const float* __restrict__ W1,
                             const float* __restrict__ W2) {
    int gid = blockIdx.x * blockDim.x + threadIdx.x;
    if (gid >= NSLOT * CHUNK_ELEMS) return;
    int slot = gid >> 13;
    int rem  = gid & 8191;
    int n = rem >> 6;
    int k = rem & 63;
    const float* W; int K; int c0;
    if (slot < 5)      { W = W0; K = CIN; c0 = slot; }
    else if (slot < 7) { W = W1; K = CH;  c0 = slot - 5; }
    else               { W = W2; K = CH;  c0 = slot - 7; }
    int kg = c0 * 64 + k;
    float v = (kg < K) ? W[(size_t)kg * CH + n] : 0.0f;
    __nv_bfloat16 hi = __float2bfloat16(v);
    __nv_bfloat16 lo = __float2bfloat16(v - __bfloat162float(hi));
    g_WtHi[gid] = hi;
    g_WtLo[gid] = lo;
}

// ---------------- fused kernel: per-batch GEMM + agg --------------------------
// AG:   A from fp32 global x (split on the fly).  else: A copied from g_Hhi/lo.
// LAST: agg writes fp32 to out.                   else: BN+ReLU, bf16 hi/lo.
template<bool AG, bool LAST>
__global__ void __launch_bounds__(256, 2) fused_layer(
    const float* __restrict__ xA, int K, int nchunks,
    const __nv_bfloat16* __restrict__ aHi,
    const __nv_bfloat16* __restrict__ aLo,
    const __nv_bfloat16* __restrict__ wtHi,
    const __nv_bfloat16* __restrict__ wtLo,
    const float* __restrict__ bias,
    const float* __restrict__ bnw, const float* __restrict__ bnb,
    float* __restrict__ outf,
    __nv_bfloat16* __restrict__ oh, __nv_bfloat16* __restrict__ ol)
{
    extern __shared__ char smc[];
    const uint32_t s0 = smem_u32(smc);
    uint32_t* sAh = (uint32_t*)(smc + OFF_AH);
    uint32_t* sAl = (uint32_t*)(smc + OFF_AL);
    uint32_t* sBh = (uint32_t*)(smc + OFF_BH);
    uint32_t* sBl = (uint32_t*)(smc + OFF_BL);
    int2*     edg = (int2*)(smc + OFF_EDG);
    int*      ptr = (int*)(smc + OFF_PTR);

    const int tid  = threadIdx.x;
    const int wid  = tid >> 5;
    const int lane = tid & 31;
    const int g    = lane >> 2;
    const int tig  = lane & 3;
    const int warpM = wid & 1;      // 0..1 (80 rows each)
    const int warpN = wid >> 1;     // 0..3 (32 cols each)
    const int b    = blockIdx.x;
    const size_t rowbase = (size_t)b * NN;

    // stage edge list once (covered by the first __syncthreads in the k-loop)
    for (int i = tid; i < ETOT; i += 256) edg[i] = g_edge[i];
    if (tid <= NN) ptr[tid] = g_ptr[tid];

    float acc[5][4][4];
#pragma unroll
    for (int mf = 0; mf < 5; mf++)
#pragma unroll
        for (int nf = 0; nf < 4; nf++)
#pragma unroll
            for (int q = 0; q < 4; q++) acc[mf][nf][q] = 0.0f;

    // ldmatrix lane-relative offsets
    const int aRow0 = warpM * 80 + (lane & 7) + ((lane >> 3) & 1) * 8;
    const uint32_t aKoff = ((lane >> 4) & 1) * 16;
    const int bRow0 = warpN * 32 + (lane & 7) + ((lane >> 4) & 1) * 8;
    const uint32_t bKoff = ((lane >> 3) & 1) * 16;
    uint32_t aRel[5], bRel[2];
#pragma unroll
    for (int mf = 0; mf < 5; mf++)
        aRel[mf] = (uint32_t)(aRow0 + mf * 16) * AWB + aKoff;
#pragma unroll
    for (int nfp = 0; nfp < 2; nfp++)
        bRel[nfp] = (uint32_t)(bRow0 + nfp * 16) * AWB + bKoff;

    const uint32_t* gh32 = (const uint32_t*)wtHi;
    const uint32_t* gl32 = (const uint32_t*)wtLo;

    for (int t = 0; t < nchunks; t++) {
        if (t) __syncthreads();

        // ---- stage A ----
        if (AG) {
            // fp32 -> bf16 hi/lo split: 160 rows x 32 packed words (128 B/row)
#pragma unroll
            for (int p = 0; p < 20; p++) {
                int idx = tid + p * 256;
                int m = idx >> 5, kp = idx & 31;
                int kg = t * 64 + kp * 2;
                float v0 = 0.0f, v1 = 0.0f;
                if (m < NN) {
                    const float* ap = xA + (rowbase + m) * (size_t)K + kg;
                    v0 = (kg < K)     ? ap[0] : 0.0f;
                    v1 = (kg + 1 < K) ? ap[1] : 0.0f;
                }
                float h0f = __bfloat162float(__float2bfloat16(v0));
                float h1f = __bfloat162float(__float2bfloat16(v1));
                sAh[m * AW + kp] = bf16x2_pack(h0f, h1f);
                sAl[m * AW + kp] = bf16x2_pack(v0 - h0f, v1 - h1f);
            }
        } else {
            // pure copy of pre-split H: 2 arrays x 160 rows x 8 uint4 (128 B/row)
#pragma unroll
            for (int p = 0; p < 10; p++) {
                int idx = tid + p * 256;      // 0..2559
                int arr = idx >= 1280;
                int rem = arr ? idx - 1280 : idx;
                int m = rem >> 3, gg = rem & 7;   // m 0..159, gg 0..7 (16B)
                uint4 v = make_uint4(0, 0, 0, 0);
                if (m < NN) {
                    const __nv_bfloat16* src = (arr ? aLo : aHi) +
                        (rowbase + m) * CH + t * 64;
                    v = *(const uint4*)((const char*)src + gg * 16);
                }
                uint32_t* dst = arr ? sAl : sAh;
                *(uint4*)((char*)(dst + m * AW) + gg * 16) = v;
            }
        }
        // ---- stage B ----
        const uint32_t* gh = gh32 + t * 4096;
        const uint32_t* gl = gl32 + t * 4096;
#pragma unroll
        for (int p = 0; p < 16; p++) {
            int idx = tid + p * 256;
            int n = idx >> 5, w = idx & 31;
            sBh[n * AW + w] = gh[n * 32 + w];
            sBl[n * AW + w] = gl[n * 32 + w];
        }
        __syncthreads();

        // ---- compute: 4 k16 steps ----
        const uint32_t sAH = s0 + OFF_AH, sAL = s0 + OFF_AL;
        const uint32_t sBH = s0 + OFF_BH, sBL = s0 + OFF_BL;
#pragma unroll
        for (int ks = 0; ks < 4; ks++) {
            const uint32_t kb = (uint32_t)ks * 32;
            uint32_t bh[2][4], bl[2][4];
#pragma unroll
            for (int nfp = 0; nfp < 2; nfp++) {
                ldsm_x4(bh[nfp], sBH + bRel[nfp] + kb);
                ldsm_x4(bl[nfp], sBL + bRel[nfp] + kb);
            }
#pragma unroll
            for (int mf = 0; mf < 5; mf++) {
                uint32_t ah[4], al[4];
                ldsm_x4(ah, sAH + aRel[mf] + kb);
                ldsm_x4(al, sAL + aRel[mf] + kb);
#pragma unroll
                for (int nfp = 0; nfp < 2; nfp++)
#pragma unroll
                    for (int h = 0; h < 2; h++) {
                        int nf = nfp * 2 + h;
                        uint32_t b0 = bh[nfp][h * 2], b1 = bh[nfp][h * 2 + 1];
                        uint32_t c0 = bl[nfp][h * 2], c1 = bl[nfp][h * 2 + 1];
                        mma16816(acc[mf][nf], ah, b0, b1);
                        mma16816(acc[mf][nf], ah, c0, c1);
                        mma16816(acc[mf][nf], al, b0, b1);
                    }
            }
        }
    }
    __syncthreads();   // all smem reads done; T overlays A/B

    // ---- epilogue: fragments -> smem T [156][132] fp32 ----
    float* T = (float*)(smc + OFF_T);
#pragma unroll
    for (int mf = 0; mf < 5; mf++) {
#pragma unroll
        for (int nf = 0; nf < 4; nf++) {
            int row = warpM * 80 + mf * 16 + g;
            int col = warpN * 32 + nf * 8 + tig * 2;
            if (row < NN)
                *(float2*)&T[row * 132 + col] =
                    make_float2(acc[mf][nf][0], acc[mf][nf][1]);
            if (row + 8 < NN)
                *(float2*)&T[(row + 8) * 132 + col] =
                    make_float2(acc[mf][nf][2], acc[mf][nf][3]);
        }
    }
    __syncthreads();

    // ---- aggregation: warp-per-row, lane = 4 channels ----
    const float4* T4 = (const float4*)T;   // row stride 33 float4
    float4 bias4 = ((const float4*)bias)[lane];
    float4 bnw4 = make_float4(0, 0, 0, 0), bnb4 = make_float4(0, 0, 0, 0);
    if (!LAST) {
        bnw4 = ((const float4*)bnw)[lane];
        bnw4.x *= BN_INV_SQRT; bnw4.y *= BN_INV_SQRT;
        bnw4.z *= BN_INV_SQRT; bnw4.w *= BN_INV_SQRT;
        bnb4 = ((const float4*)bnb)[lane];
    }

    for (int n = wid; n < NN; n += 8) {
        int e = ptr[n];
        const int end = ptr[n + 1];
        float4 a0 = make_float4(0, 0, 0, 0);
        float4 a1 = make_float4(0, 0, 0, 0);
        for (; e + 1 < end; e += 2) {
            int2 e0 = edg[e], e1 = edg[e + 1];
            float4 t0 = T4[e0.x * 33 + lane];
            float4 t1 = T4[e1.x * 33 + lane];
            float m0 = __int_as_float(e0.y);
            float m1 = __int_as_float(e1.y);
            a0.x = fmaf(t0.x, m0, a0.x); a0.y = fmaf(t0.y, m0, a0.y);
            a0.z = fmaf(t0.z, m0, a0.z); a0.w = fmaf(t0.w, m0, a0.w);
            a1.x = fmaf(t1.x, m1, a1.x); a1.y = fmaf(t1.y, m1, a1.y);
            a1.z = fmaf(t1.z, m1, a1.z); a1.w = fmaf(t1.w, m1, a1.w);
        }
        if (e < end) {
            int2 e0 = edg[e];
            float4 t0 = T4[e0.x * 33 + lane];
            float m0 = __int_as_float(e0.y);
            a0.x = fmaf(t0.x, m0, a0.x); a0.y = fmaf(t0.y, m0, a0.y);
            a0.z = fmaf(t0.z, m0, a0.z); a0.w = fmaf(t0.w, m0, a0.w);
        }
        float4 v;
        v.x = a0.x + a1.x + bias4.x;
        v.y = a0.y + a1.y + bias4.y;
        v.z = a0.z + a1.z + bias4.z;
        v.w = a0.w + a1.w + bias4.w;
        const size_t ofs = (rowbase + n) * CH + lane * 4;
        if (LAST) {
            *(float4*)(outf + ofs) = v;
        } else {
            v.x = fmaxf(fmaf(v.x, bnw4.x, bnb4.x), 0.0f);
            v.y = fmaxf(fmaf(v.y, bnw4.y, bnb4.y), 0.0f);
            v.z = fmaxf(fmaf(v.z, bnw4.z, bnb4.z), 0.0f);
            v.w = fmaxf(fmaf(v.w, bnw4.w, bnb4.w), 0.0f);
            __nv_bfloat16 hx = __float2bfloat16(v.x);
            __nv_bfloat16 hy = __float2bfloat16(v.y);
            __nv_bfloat16 hz = __float2bfloat16(v.z);
            __nv_bfloat16 hw = __float2bfloat16(v.w);
            float fx = __bfloat162float(hx), fy = __bfloat162float(hy);
            float fz = __bfloat162float(hz), fw = __bfloat162float(hw);
            uint2 hv, lv;
            hv.x = ((uint32_t)__bfloat16_as_ushort(hy) << 16) |
                   __bfloat16_as_ushort(hx);
            hv.y = ((uint32_t)__bfloat16_as_ushort(hw) << 16) |
                   __bfloat16_as_ushort(hz);
            lv.x = bf16x2_pack(v.x - fx, v.y - fy);
            lv.y = bf16x2_pack(v.z - fz, v.w - fw);
            *(uint2*)(oh + ofs) = hv;
            *(uint2*)(ol + ofs) = lv;
        }
    }
}

// ---------------- launch ----------------------------------------------------
extern "C" void kernel_launch(void* const* d_in, const int* in_sizes, int n_in,
                              void* d_out, int out_size)
{
    const float* x    = (const float*)d_in[0];
    const void*  ei   = d_in[1];
    const float* W0   = (const float*)d_in[2];
    const float* b0   = (const float*)d_in[3];
    const float* bnw0 = (const float*)d_in[4];
    const float* bnb0 = (const float*)d_in[5];
    const float* W1   = (const float*)d_in[6];
    const float* b1   = (const float*)d_in[7];
    const float* bnw1 = (const float*)d_in[8];
    const float* bnb1 = (const float*)d_in[9];
    const float* W2   = (const float*)d_in[10];
    const float* b2   = (const float*)d_in[11];
    float*       out  = (float*)d_out;

    __nv_bfloat16 *hh, *hl, *wh, *wl;
    cudaGetSymbolAddress((void**)&hh, g_Hhi);
    cudaGetSymbolAddress((void**)&hl, g_Hlo);
    cudaGetSymbolAddress((void**)&wh, g_WtHi);
    cudaGetSymbolAddress((void**)&wl, g_WtLo);

    cudaFuncSetAttribute(fused_layer<true, false>,
                         cudaFuncAttributeMaxDynamicSharedMemorySize, SMEM_FUSED);
    cudaFuncSetAttribute(fused_layer<false, false>,
                         cudaFuncAttributeMaxDynamicSharedMemorySize, SMEM_FUSED);
    cudaFuncSetAttribute(fused_layer<false, true>,
                         cudaFuncAttributeMaxDynamicSharedMemorySize, SMEM_FUSED);

    // build x2 (idempotent) so ncu -s 5 -c 1 captures fused layer 2 (#6).
    build_kernel<<<1, 256>>>(ei);                                     // 1
    build_kernel<<<1, 256>>>(ei);                                     // 2
    wprep_kernel<<<(NSLOT * CHUNK_ELEMS + 511) / 512, 512>>>(W0, W1, W2); // 3

    // layer 0: x @ W0 -> agg -> H (bf16 hi/lo)
    fused_layer<true, false><<<BATCH, 256, SMEM_FUSED>>>(
        x, CIN, 5, nullptr, nullptr, wh, wl,
        b0, bnw0, bnb0, nullptr, hh, hl);                             // 4
    // layer 1: H @ W1 -> agg -> H
    fused_layer<false, false><<<BATCH, 256, SMEM_FUSED>>>(
        nullptr, CH, 2, hh, hl, wh + 5 * CHUNK_ELEMS, wl + 5 * CHUNK_ELEMS,
        b1, bnw1, bnb1, nullptr, hh, hl);                             // 5
    // layer 2: H @ W2 -> agg -> out (fp32)
    fused_layer<false, true><<<BATCH, 256, SMEM_FUSED>>>(
        nullptr, CH, 2, hh, hl, wh + 7 * CHUNK_ELEMS, wl + 7 * CHUNK_ELEMS,
        b2, nullptr, nullptr, out, nullptr, nullptr);                 // 6 <- ncu
}